// round 8
// baseline (speedup 1.0000x reference)
#include <cuda_runtime.h>
#include <math.h>

// ---------------- problem constants ----------------
#define NE_    100000
#define NR_    200
#define RDIM_  384
#define BB     8192
#define NCOL   406          // 6 scalar cols + 2*NR
#define GAMMA_F 12.0f
#define NM_SPLIT 92         // n's per (row,side) computed on the MUFU pipe; rest via smem table

// ---------------- scratch (__device__ globals; no allocs allowed) ----------------
__device__ float  g_Wc[512 * 256];        // folded e_p_emb weight  (512 KB)
__device__ float  g_P[2 * BB * 256];      // e_p: s rows [0,B), o rows [B,2B)  (16 MB)
__device__ float  g_scabs[BB];            // per-row sc_abs
__device__ float2 g_TW[2 * BB * 200];     // per (row-side, n): (t as float, w)  (26 MB)
__device__ float2 g_T[8 * 1000 * 16];     // pos-emb table, slice-major [slice][t][dd] (1 MB)
__device__ float  g_prel[8 * BB];         // per-slice partial sc_rel sums

// ======================================================================
// Kernel 0a: fold w_e (512x128) into the single real GEMM weight Wc (512x256)
// ======================================================================
__global__ void k_wc(const float* __restrict__ w_e) {
    int k = blockIdx.x;        // 0..511
    int j = threadIdx.x;       // 0..255
    float v;
    if (j < 128) {
        v = w_e[k * 128 + j];
        if (k >= 256) v = -v;
    } else {
        v = w_e[(k ^ 256) * 128 + (j - 128)];
        if (k < 256) v = -v;
    }
    g_Wc[k * 256 + j] = v;
}

// ======================================================================
// Kernel 0b: build pos-emb table T[t][d] = (cos(t*f_d), sin(t*f_d)),
// stored slice-major: g_T[(d>>4)*1000 + t][d&15]
// ======================================================================
__global__ void k_tbuild() {
    int t = blockIdx.x;        // 0..999
    int d = threadIdx.x;       // 0..127
    float f = exp2f(-(float)d * (13.287712379549449f / 128.0f));
    float s, c;
    sincosf((float)t * f, &s, &c);
    g_T[((d >> 4) * 1000 + t) * 16 + (d & 15)] = make_float2(c, s);
}

// ======================================================================
// Kernel 1: per row — t_emb + sc_abs, and prestage (t, w) pairs into g_TW
// ======================================================================
__global__ void __launch_bounds__(256) k_gather(
    const int* __restrict__ x, int xs,
    const float* __restrict__ e_emb,
    const float* __restrict__ r_emb,
    const float* __restrict__ d_frq, const float* __restrict__ d_phi,
    const float* __restrict__ d_amp,
    const float* __restrict__ m_frq, const float* __restrict__ m_phi,
    const float* __restrict__ m_amp,
    const float* __restrict__ w_rp)
{
    __shared__ float st[256];
    __shared__ float ot[256];
    __shared__ float red8[8];

    const int b   = blockIdx.x;
    const int tid = threadIdx.x;
    const int base = b * NCOL;

    const int s_idx = x[(base + 0) * xs];
    const int r_idx = x[(base + 1) * xs];
    const int o_idx = x[(base + 2) * xs];
    const float dv  = (float)x[(base + 3) * xs];
    const float mv  = (float)x[(base + 4) * xs];

    // ---- stage (t, w) into g_TW: cols 6..205 = c_s, 206..405 = c_o ----
    for (int i = tid; i < 400; i += 256) {
        int side = i / 200;
        int n    = i - side * 200;
        int t    = x[(base + 6 + i) * xs];
        float w  = w_rp[r_idx * 200 + n];
        g_TW[(size_t)(side ? (BB + b) : b) * 200 + n] = make_float2((float)t, w);
    }

    // ---- t_emb (j = tid covers all 256 dims) ----
    {
        const int j  = tid;
        const int jm = (j < 128) ? j : (j - 128);
        {
            const size_t e = (size_t)s_idx;
            float angd = fmaf(dv, d_frq[e * 256 + j], d_phi[e * 256 + j]);
            float angm = fmaf(mv, m_frq[e * 256 + j], m_phi[e * 256 + j]);
            float ad = d_amp[e * 128 + jm];
            float am = m_amp[e * 128 + jm];
            st[j] = (j < 128) ? (ad * __cosf(angd) + am * __cosf(angm))
                              : (ad * __sinf(angd) + am * __sinf(angm));
        }
        {
            const size_t e = (size_t)o_idx;
            float angd = fmaf(dv, d_frq[e * 256 + j], d_phi[e * 256 + j]);
            float angm = fmaf(mv, m_frq[e * 256 + j], m_phi[e * 256 + j]);
            float ad = d_amp[e * 128 + jm];
            float am = m_amp[e * 128 + jm];
            ot[j] = (j < 128) ? (ad * __cosf(angd) + am * __cosf(angm))
                              : (ad * __sinf(angd) + am * __sinf(angm));
        }
    }
    __syncthreads();

    // ---- sc_abs over k = 0..383 ----
    const float scale = (float)(3.141592653589793 / sqrt(6.0 / (double)(NR_ + RDIM_)));
    const size_t sb = (size_t)s_idx * 512;
    const size_t ob = (size_t)o_idx * 512;
    float sum = 0.0f;
    for (int k = tid; k < 384; k += 256) {
        float pr = r_emb[(size_t)r_idx * 384 + k] * scale;
        float sn, cs;
        __sincosf(pr, &sn, &cs);
        float re_s, im_s, re_o, im_o;
        if (k < 256) {
            re_s = e_emb[sb + k];
            im_s = e_emb[sb + 256 + k];
            re_o = e_emb[ob + k];
            im_o = e_emb[ob + 256 + k];
        } else {
            re_s = st[k - 256];  im_s = st[k - 128];
            re_o = ot[k - 256];  im_o = ot[k - 128];
        }
        float re = re_s * cs - im_s * sn - re_o;
        float im = re_s * sn + im_s * cs - im_o;
        sum += sqrtf(re * re + im * im);
    }

    #pragma unroll
    for (int off = 16; off; off >>= 1) sum += __shfl_down_sync(0xffffffffu, sum, off);
    if ((tid & 31) == 0) red8[tid >> 5] = sum;
    __syncthreads();
    if (tid == 0) {
        float t = 0.0f;
        #pragma unroll
        for (int i = 0; i < 8; i++) t += red8[i];
        g_scabs[b] = t;
    }
}

// ======================================================================
// Kernel 2: gathered-A SGEMM  P[m][j] = sum_k e_emb[idx_m][k] * Wc[k][j]
//   BM=128, BN=128, BK=8, 256 threads, TM=8 x TN=8
// ======================================================================
__global__ void __launch_bounds__(256, 2) k_gemm(
    const float* __restrict__ e_emb,
    const int* __restrict__ x, int xs)
{
    __shared__ float As[8][128];
    __shared__ float Bs[8][128];
    __shared__ int   idx_s[128];

    const int tid = threadIdx.x;
    const int bn = blockIdx.x * 128;
    const int bm = blockIdx.y * 128;

    if (tid < 128) {
        int gr = bm + tid;
        idx_s[tid] = (gr < BB) ? x[(gr * NCOL + 0) * xs]
                               : x[((gr - BB) * NCOL + 2) * xs];
    }
    __syncthreads();

    const int ar = tid >> 1;             // A row 0..127
    const int ak = (tid & 1) * 4;        // k offset 0 / 4
    const float* aptr = e_emb + (size_t)idx_s[ar] * 512 + ak;
    const int bkr = tid >> 5;            // B k-row 0..7
    const int bnc = (tid & 31) * 4;      // B col 0..124
    const int tx = tid & 15;             // n sub-tile
    const int ty = tid >> 4;             // m sub-tile

    float acc[8][8];
    #pragma unroll
    for (int i = 0; i < 8; i++)
        #pragma unroll
        for (int j = 0; j < 8; j++) acc[i][j] = 0.0f;

    for (int k0 = 0; k0 < 512; k0 += 8) {
        float4 a4 = *reinterpret_cast<const float4*>(aptr + k0);
        As[ak + 0][ar] = a4.x; As[ak + 1][ar] = a4.y;
        As[ak + 2][ar] = a4.z; As[ak + 3][ar] = a4.w;
        float4 b4 = *reinterpret_cast<const float4*>(&g_Wc[(k0 + bkr) * 256 + bn + bnc]);
        *reinterpret_cast<float4*>(&Bs[bkr][bnc]) = b4;
        __syncthreads();

        #pragma unroll
        for (int k = 0; k < 8; k++) {
            float4 a0 = *reinterpret_cast<const float4*>(&As[k][ty * 8]);
            float4 a1 = *reinterpret_cast<const float4*>(&As[k][ty * 8 + 4]);
            float4 b0 = *reinterpret_cast<const float4*>(&Bs[k][tx * 8]);
            float4 b1 = *reinterpret_cast<const float4*>(&Bs[k][tx * 8 + 4]);
            float av[8] = {a0.x, a0.y, a0.z, a0.w, a1.x, a1.y, a1.z, a1.w};
            float bv[8] = {b0.x, b0.y, b0.z, b0.w, b1.x, b1.y, b1.z, b1.w};
            #pragma unroll
            for (int i = 0; i < 8; i++)
                #pragma unroll
                for (int j = 0; j < 8; j++)
                    acc[i][j] = fmaf(av[i], bv[j], acc[i][j]);
        }
        __syncthreads();
    }

    #pragma unroll
    for (int i = 0; i < 8; i++) {
        int row = bm + ty * 8 + i;
        float* dst = &g_P[(size_t)row * 256 + bn + tx * 8];
        *reinterpret_cast<float4*>(dst)     = make_float4(acc[i][0], acc[i][1], acc[i][2], acc[i][3]);
        *reinterpret_cast<float4*>(dst + 4) = make_float4(acc[i][4], acc[i][5], acc[i][6], acc[i][7]);
    }
}

// ======================================================================
// Kernel 3: e_r_emb + sc_rel via hybrid MUFU / smem-table, d-sliced.
// grid = 8 slices x 37 row-blocks = 296 blocks (exactly 2 waves @ 1 blk/SM).
// Block: 256 thr = 32 row-lanes (g) x 8 d-pairs (dd2); 128 KB table slice in smem.
// ======================================================================
__global__ void __launch_bounds__(256, 1) k_rel() {
    extern __shared__ float4 ts4[];            // [1000][8] float4 = 128 KB
    const int tid   = threadIdx.x;
    const int slice = blockIdx.x & 7;
    const int bj    = blockIdx.x >> 3;         // 0..36
    const int row_begin = bj * 222;
    const int row_end   = min(BB, row_begin + 222);

    // load this slice's table (contiguous 128 KB, coalesced)
    const float4* gt4 = reinterpret_cast<const float4*>(g_T) + (size_t)slice * 8000;
    for (int i = tid; i < 8000; i += 256) ts4[i] = gt4[i];
    __syncthreads();

    const int dd2 = tid & 7;                   // d-pair within slice
    const int g   = tid >> 3;                  // row lane 0..31
    const int d0  = slice * 16 + dd2 * 2;
    const float LOGK = 13.287712379549449f / 128.0f;
    const float f0 = exp2f(-(float)d0 * LOGK);
    const float f1 = exp2f(-(float)(d0 + 1) * LOGK);

    for (int row = row_begin + g; row < row_end; row += 32) {
        float acc[2][4];
        #pragma unroll
        for (int s2 = 0; s2 < 2; s2++)
            #pragma unroll
            for (int j = 0; j < 4; j++) acc[s2][j] = 0.0f;

        #pragma unroll
        for (int side = 0; side < 2; side++) {
            const float2* tw = g_TW + (size_t)(side * BB + row) * 200;
            float a0 = 0.f, a1 = 0.f, a2 = 0.f, a3 = 0.f;

            // --- MUFU part: keeps the SFU pipe busy while other warps hit smem ---
            #pragma unroll 4
            for (int n = 0; n < NM_SPLIT; n++) {
                float2 v = __ldg(&tw[n]);
                float s0, c0, s1, c1;
                __sincosf(v.x * f0, &s0, &c0);
                __sincosf(v.x * f1, &s1, &c1);
                a0 = fmaf(v.y, c0, a0); a1 = fmaf(v.y, s0, a1);
                a2 = fmaf(v.y, c1, a2); a3 = fmaf(v.y, s1, a3);
            }
            // --- table part: t is an exact small integer -> smem lookup ---
            #pragma unroll 4
            for (int n = NM_SPLIT; n < 200; n++) {
                float2 v = __ldg(&tw[n]);
                int ti = (int)v.x;
                float4 cs = ts4[ti * 8 + dd2];  // (cos d0, sin d0, cos d0+1, sin d0+1)
                a0 = fmaf(v.y, cs.x, a0); a1 = fmaf(v.y, cs.y, a1);
                a2 = fmaf(v.y, cs.z, a2); a3 = fmaf(v.y, cs.w, a3);
            }
            acc[side][0] = a0; acc[side][1] = a1;
            acc[side][2] = a2; acc[side][3] = a3;
        }

        // epilogue: add projection P, pairwise distance over this thread's 2 d's
        const float* Ps = g_P + (size_t)row * 256;
        const float* Po = g_P + (size_t)(BB + row) * 256;
        float dre0 = (acc[0][0] + Ps[d0])       - (acc[1][0] + Po[d0]);
        float dim0 = (acc[0][1] + Ps[d0 + 128]) - (acc[1][1] + Po[d0 + 128]);
        float dre1 = (acc[0][2] + Ps[d0 + 1])   - (acc[1][2] + Po[d0 + 1]);
        float dim1 = (acc[0][3] + Ps[d0 + 129]) - (acc[1][3] + Po[d0 + 129]);
        float v = sqrtf(dre0 * dre0 + dim0 * dim0) + sqrtf(dre1 * dre1 + dim1 * dim1);

        // reduce over the 8 dd2 lanes of this row group
        v += __shfl_down_sync(0xffffffffu, v, 4, 8);
        v += __shfl_down_sync(0xffffffffu, v, 2, 8);
        v += __shfl_down_sync(0xffffffffu, v, 1, 8);
        if (dd2 == 0) g_prel[slice * BB + row] = v;
    }
}

// ======================================================================
// Kernel 4: final combine
// ======================================================================
__global__ void k_out(float* __restrict__ out) {
    int b = blockIdx.x * 256 + threadIdx.x;
    if (b < BB) {
        float s = g_scabs[b];
        #pragma unroll
        for (int i = 0; i < 8; i++) s += g_prel[i * BB + b];
        out[b] = GAMMA_F - s;
    }
}

// ======================================================================
// launcher
// ======================================================================
extern "C" void kernel_launch(void* const* d_in, const int* in_sizes, int n_in,
                              void* d_out, int out_size)
{
    const int*   x     = (const int*)  d_in[0];
    const float* e_emb = (const float*)d_in[1];
    const float* r_emb = (const float*)d_in[2];
    const float* d_frq = (const float*)d_in[3];
    const float* d_phi = (const float*)d_in[4];
    const float* d_amp = (const float*)d_in[5];
    const float* m_frq = (const float*)d_in[6];
    const float* m_phi = (const float*)d_in[7];
    const float* m_amp = (const float*)d_in[8];
    const float* w_e   = (const float*)d_in[9];
    const float* w_rp  = (const float*)d_in[10];
    float* out = (float*)d_out;

    // x arrives as int64 reported in int32 words; infer element stride.
    int xs = in_sizes[0] / (BB * NCOL);
    if (xs < 1) xs = 1;

    cudaFuncSetAttribute(k_rel, cudaFuncAttributeMaxDynamicSharedMemorySize, 128 * 1024);

    k_wc<<<512, 256>>>(w_e);
    k_tbuild<<<1000, 128>>>();
    k_gather<<<BB, 256>>>(x, xs, e_emb, r_emb, d_frq, d_phi, d_amp,
                          m_frq, m_phi, m_amp, w_rp);
    k_gemm<<<dim3(2, 128), 256>>>(e_emb, x, xs);
    k_rel<<<296, 256, 128 * 1024>>>();
    k_out<<<32, 256>>>(out);
}

// round 9
// speedup vs baseline: 1.8931x; 1.8931x over previous
#include <cuda_runtime.h>
#include <cuda_bf16.h>
#include <math.h>

// ---------------- problem constants ----------------
#define NE_    100000
#define NR_    200
#define RDIM_  384
#define BB     8192
#define NCOL   406          // 6 scalar cols + 2*NR
#define GAMMA_F 12.0f
#define NS     52           // n's per (row,side) on the MUFU pipe; rest via bf16 smem table
#define NSLICE 4            // d sliced into 4 groups of 32
#define RB     38           // row-blocks per slice: 4*38 = 152 blocks = 1 wave on GB300
#define ROWS_PER_BLK 216    // ceil(8192/38)

// ---------------- scratch (__device__ globals; no allocs allowed) ----------------
__device__ float  g_Wc[512 * 256];              // folded e_p_emb weight (512 KB)
__device__ float  g_P[2 * BB * 256];            // e_p: s rows [0,B), o rows [B,2B) (16 MB)
__device__ float  g_scabs[BB];                  // per-row sc_abs
__device__ float2 g_TW[2 * BB * 200];           // per (row-side, n): (t as float, w) (26 MB)
__device__ uint4  g_Tb[NSLICE * 1000 * 8];      // bf16 pos-emb table, slice-major (512 KB)
__device__ float  g_prel[NSLICE * BB];          // per-slice partial sc_rel sums

#define LOGK (13.287712379549449f / 128.0f)     // log2(10000)/128

// ======================================================================
// Kernel 0a: fold w_e (512x128) into single real GEMM weight Wc (512x256)
// ======================================================================
__global__ void k_wc(const float* __restrict__ w_e) {
    int k = blockIdx.x;        // 0..511
    int j = threadIdx.x;       // 0..255
    float v;
    if (j < 128) {
        v = w_e[k * 128 + j];
        if (k >= 256) v = -v;
    } else {
        v = w_e[(k ^ 256) * 128 + (j - 128)];
        if (k < 256) v = -v;
    }
    g_Wc[k * 256 + j] = v;
}

// ======================================================================
// Kernel 0b: build bf16 pos-emb table.
// Layout: slice s = d>>5 covers d in [32s, 32s+32). Within slice, per t:
// 8 quads dq = (d>>2)&7; quad = uint4 of 8 bf16: (c0,s0,c1,s1,c2,s2,c3,s3).
// ======================================================================
__global__ void k_tbuild() {
    int t = blockIdx.x;        // 0..999
    int d = threadIdx.x;       // 0..127
    float f = exp2f(-(float)d * LOGK);
    float s, c;
    sincosf((float)t * f, &s, &c);   // full-precision build (one-time)
    int slice = d >> 5, dq = (d >> 2) & 7, e = d & 3;
    __nv_bfloat16* dst = reinterpret_cast<__nv_bfloat16*>(
        &g_Tb[((size_t)slice * 1000 + t) * 8 + dq]);
    dst[e * 2 + 0] = __float2bfloat16(c);
    dst[e * 2 + 1] = __float2bfloat16(s);
}

// ======================================================================
// Kernel 1: per row — t_emb + sc_abs, and prestage (t, w) pairs into g_TW
// ======================================================================
__global__ void __launch_bounds__(256) k_gather(
    const int* __restrict__ x, int xs,
    const float* __restrict__ e_emb,
    const float* __restrict__ r_emb,
    const float* __restrict__ d_frq, const float* __restrict__ d_phi,
    const float* __restrict__ d_amp,
    const float* __restrict__ m_frq, const float* __restrict__ m_phi,
    const float* __restrict__ m_amp,
    const float* __restrict__ w_rp)
{
    __shared__ float st[256];
    __shared__ float ot[256];
    __shared__ float red8[8];

    const int b   = blockIdx.x;
    const int tid = threadIdx.x;
    const int base = b * NCOL;

    const int s_idx = x[(base + 0) * xs];
    const int r_idx = x[(base + 1) * xs];
    const int o_idx = x[(base + 2) * xs];
    const float dv  = (float)x[(base + 3) * xs];
    const float mv  = (float)x[(base + 4) * xs];

    // stage (t, w) into g_TW: cols 6..205 = c_s, 206..405 = c_o
    for (int i = tid; i < 400; i += 256) {
        int side = i / 200;
        int n    = i - side * 200;
        int t    = x[(base + 6 + i) * xs];
        float w  = w_rp[r_idx * 200 + n];
        g_TW[(size_t)(side ? (BB + b) : b) * 200 + n] = make_float2((float)t, w);
    }

    // t_emb (j = tid covers all 256 dims)
    {
        const int j  = tid;
        const int jm = (j < 128) ? j : (j - 128);
        {
            const size_t e = (size_t)s_idx;
            float angd = fmaf(dv, d_frq[e * 256 + j], d_phi[e * 256 + j]);
            float angm = fmaf(mv, m_frq[e * 256 + j], m_phi[e * 256 + j]);
            float ad = d_amp[e * 128 + jm];
            float am = m_amp[e * 128 + jm];
            st[j] = (j < 128) ? (ad * __cosf(angd) + am * __cosf(angm))
                              : (ad * __sinf(angd) + am * __sinf(angm));
        }
        {
            const size_t e = (size_t)o_idx;
            float angd = fmaf(dv, d_frq[e * 256 + j], d_phi[e * 256 + j]);
            float angm = fmaf(mv, m_frq[e * 256 + j], m_phi[e * 256 + j]);
            float ad = d_amp[e * 128 + jm];
            float am = m_amp[e * 128 + jm];
            ot[j] = (j < 128) ? (ad * __cosf(angd) + am * __cosf(angm))
                              : (ad * __sinf(angd) + am * __sinf(angm));
        }
    }
    __syncthreads();

    // sc_abs over k = 0..383
    const float scale = (float)(3.141592653589793 / sqrt(6.0 / (double)(NR_ + RDIM_)));
    const size_t sb = (size_t)s_idx * 512;
    const size_t ob = (size_t)o_idx * 512;
    float sum = 0.0f;
    for (int k = tid; k < 384; k += 256) {
        float pr = r_emb[(size_t)r_idx * 384 + k] * scale;
        float sn, cs;
        __sincosf(pr, &sn, &cs);
        float re_s, im_s, re_o, im_o;
        if (k < 256) {
            re_s = e_emb[sb + k];
            im_s = e_emb[sb + 256 + k];
            re_o = e_emb[ob + k];
            im_o = e_emb[ob + 256 + k];
        } else {
            re_s = st[k - 256];  im_s = st[k - 128];
            re_o = ot[k - 256];  im_o = ot[k - 128];
        }
        float re = re_s * cs - im_s * sn - re_o;
        float im = re_s * sn + im_s * cs - im_o;
        sum += sqrtf(re * re + im * im);
    }

    #pragma unroll
    for (int off = 16; off; off >>= 1) sum += __shfl_down_sync(0xffffffffu, sum, off);
    if ((tid & 31) == 0) red8[tid >> 5] = sum;
    __syncthreads();
    if (tid == 0) {
        float t = 0.0f;
        #pragma unroll
        for (int i = 0; i < 8; i++) t += red8[i];
        g_scabs[b] = t;
    }
}

// ======================================================================
// Kernel 2: gathered-A SGEMM  P[m][j] = sum_k e_emb[idx_m][k] * Wc[k][j]
//   BM=128, BN=128, BK=8, 256 threads, TM=8 x TN=8  (measured 124 us)
// ======================================================================
__global__ void __launch_bounds__(256, 2) k_gemm(
    const float* __restrict__ e_emb,
    const int* __restrict__ x, int xs)
{
    __shared__ float As[8][128];
    __shared__ float Bs[8][128];
    __shared__ int   idx_s[128];

    const int tid = threadIdx.x;
    const int bn = blockIdx.x * 128;
    const int bm = blockIdx.y * 128;

    if (tid < 128) {
        int gr = bm + tid;
        idx_s[tid] = (gr < BB) ? x[(gr * NCOL + 0) * xs]
                               : x[((gr - BB) * NCOL + 2) * xs];
    }
    __syncthreads();

    const int ar = tid >> 1;
    const int ak = (tid & 1) * 4;
    const float* aptr = e_emb + (size_t)idx_s[ar] * 512 + ak;
    const int bkr = tid >> 5;
    const int bnc = (tid & 31) * 4;
    const int tx = tid & 15;
    const int ty = tid >> 4;

    float acc[8][8];
    #pragma unroll
    for (int i = 0; i < 8; i++)
        #pragma unroll
        for (int j = 0; j < 8; j++) acc[i][j] = 0.0f;

    for (int k0 = 0; k0 < 512; k0 += 8) {
        float4 a4 = *reinterpret_cast<const float4*>(aptr + k0);
        As[ak + 0][ar] = a4.x; As[ak + 1][ar] = a4.y;
        As[ak + 2][ar] = a4.z; As[ak + 3][ar] = a4.w;
        float4 b4 = *reinterpret_cast<const float4*>(&g_Wc[(k0 + bkr) * 256 + bn + bnc]);
        *reinterpret_cast<float4*>(&Bs[bkr][bnc]) = b4;
        __syncthreads();

        #pragma unroll
        for (int k = 0; k < 8; k++) {
            float4 a0 = *reinterpret_cast<const float4*>(&As[k][ty * 8]);
            float4 a1 = *reinterpret_cast<const float4*>(&As[k][ty * 8 + 4]);
            float4 b0 = *reinterpret_cast<const float4*>(&Bs[k][tx * 8]);
            float4 b1 = *reinterpret_cast<const float4*>(&Bs[k][tx * 8 + 4]);
            float av[8] = {a0.x, a0.y, a0.z, a0.w, a1.x, a1.y, a1.z, a1.w};
            float bv[8] = {b0.x, b0.y, b0.z, b0.w, b1.x, b1.y, b1.z, b1.w};
            #pragma unroll
            for (int i = 0; i < 8; i++)
                #pragma unroll
                for (int j = 0; j < 8; j++)
                    acc[i][j] = fmaf(av[i], bv[j], acc[i][j]);
        }
        __syncthreads();
    }

    #pragma unroll
    for (int i = 0; i < 8; i++) {
        int row = bm + ty * 8 + i;
        float* dst = &g_P[(size_t)row * 256 + bn + tx * 8];
        *reinterpret_cast<float4*>(dst)     = make_float4(acc[i][0], acc[i][1], acc[i][2], acc[i][3]);
        *reinterpret_cast<float4*>(dst + 4) = make_float4(acc[i][4], acc[i][5], acc[i][6], acc[i][7]);
    }
}

// ======================================================================
// Kernel 3: e_r_emb + sc_rel, hybrid MUFU / bf16-smem-table.
// grid = 4 slices x 38 row-blocks = 152 blocks = 1 wave on GB300.
// Block: 512 thr = 64 row-lanes (g) x 8 d-quads (dq); 125 KB table slice.
// Each thread covers 4 d's (one uint4 = 8 bf16 per table lookup).
// ======================================================================
__global__ void __launch_bounds__(512, 1) k_rel() {
    extern __shared__ uint4 ts[];              // [1000][8] uint4 = 125 KB
    const int tid   = threadIdx.x;
    const int slice = blockIdx.x & 3;
    const int bj    = blockIdx.x >> 2;         // 0..37
    const int row_begin = bj * ROWS_PER_BLK;
    const int row_end   = min(BB, row_begin + ROWS_PER_BLK);

    // load this slice's table (contiguous 125 KB, coalesced)
    const uint4* gt = g_Tb + (size_t)slice * 8000;
    for (int i = tid; i < 8000; i += 512) ts[i] = gt[i];
    __syncthreads();

    const int dq = tid & 7;                    // d-quad within slice
    const int g  = tid >> 3;                   // row lane 0..63
    const int d0 = slice * 32 + dq * 4;
    float f0 = exp2f(-(float)(d0 + 0) * LOGK);
    float f1 = exp2f(-(float)(d0 + 1) * LOGK);
    float f2 = exp2f(-(float)(d0 + 2) * LOGK);
    float f3 = exp2f(-(float)(d0 + 3) * LOGK);

    for (int row = row_begin + g; row < row_end; row += 64) {
        float srel[2][8];

        #pragma unroll
        for (int side = 0; side < 2; side++) {
            const float2* tw = g_TW + (size_t)(side * BB + row) * 200;
            float re0 = 0.f, im0 = 0.f, re1 = 0.f, im1 = 0.f;
            float re2 = 0.f, im2 = 0.f, re3 = 0.f, im3 = 0.f;

            // --- MUFU part: SFU pipe ---
            #pragma unroll 4
            for (int n = 0; n < NS; n++) {
                float2 v = __ldg(&tw[n]);
                float s, c;
                __sincosf(v.x * f0, &s, &c); re0 = fmaf(v.y, c, re0); im0 = fmaf(v.y, s, im0);
                __sincosf(v.x * f1, &s, &c); re1 = fmaf(v.y, c, re1); im1 = fmaf(v.y, s, im1);
                __sincosf(v.x * f2, &s, &c); re2 = fmaf(v.y, c, re2); im2 = fmaf(v.y, s, im2);
                __sincosf(v.x * f3, &s, &c); re3 = fmaf(v.y, c, re3); im3 = fmaf(v.y, s, im3);
            }
            // --- table part: LSU + FMA pipes (t is an exact small integer) ---
            #pragma unroll 4
            for (int n = NS; n < 200; n++) {
                float2 v = __ldg(&tw[n]);
                int ti = (int)v.x;
                uint4 q = ts[ti * 8 + dq];     // 8 bf16: (c,s) x 4 d's; conflict-free
                const __nv_bfloat162* p = reinterpret_cast<const __nv_bfloat162*>(&q);
                float2 cs0 = __bfloat1622float2(p[0]);
                float2 cs1 = __bfloat1622float2(p[1]);
                float2 cs2 = __bfloat1622float2(p[2]);
                float2 cs3 = __bfloat1622float2(p[3]);
                re0 = fmaf(v.y, cs0.x, re0); im0 = fmaf(v.y, cs0.y, im0);
                re1 = fmaf(v.y, cs1.x, re1); im1 = fmaf(v.y, cs1.y, im1);
                re2 = fmaf(v.y, cs2.x, re2); im2 = fmaf(v.y, cs2.y, im2);
                re3 = fmaf(v.y, cs3.x, re3); im3 = fmaf(v.y, cs3.y, im3);
            }
            srel[side][0] = re0; srel[side][1] = im0;
            srel[side][2] = re1; srel[side][3] = im1;
            srel[side][4] = re2; srel[side][5] = im2;
            srel[side][6] = re3; srel[side][7] = im3;
        }

        // epilogue: add projection P, distances over this thread's 4 d's
        const float* Ps = g_P + (size_t)row * 256;
        const float* Po = g_P + (size_t)(BB + row) * 256;
        float4 psr = *reinterpret_cast<const float4*>(Ps + d0);
        float4 psi = *reinterpret_cast<const float4*>(Ps + d0 + 128);
        float4 por = *reinterpret_cast<const float4*>(Po + d0);
        float4 poi = *reinterpret_cast<const float4*>(Po + d0 + 128);

        float dre0 = (srel[0][0] + psr.x) - (srel[1][0] + por.x);
        float dim0 = (srel[0][1] + psi.x) - (srel[1][1] + poi.x);
        float dre1 = (srel[0][2] + psr.y) - (srel[1][2] + por.y);
        float dim1 = (srel[0][3] + psi.y) - (srel[1][3] + poi.y);
        float dre2 = (srel[0][4] + psr.z) - (srel[1][4] + por.z);
        float dim2 = (srel[0][5] + psi.z) - (srel[1][5] + poi.z);
        float dre3 = (srel[0][6] + psr.w) - (srel[1][6] + por.w);
        float dim3 = (srel[0][7] + psi.w) - (srel[1][7] + poi.w);

        float v = sqrtf(dre0 * dre0 + dim0 * dim0) + sqrtf(dre1 * dre1 + dim1 * dim1)
                + sqrtf(dre2 * dre2 + dim2 * dim2) + sqrtf(dre3 * dre3 + dim3 * dim3);

        // reduce over the 8 dq lanes of this row group
        v += __shfl_down_sync(0xffffffffu, v, 4, 8);
        v += __shfl_down_sync(0xffffffffu, v, 2, 8);
        v += __shfl_down_sync(0xffffffffu, v, 1, 8);
        if (dq == 0) g_prel[slice * BB + row] = v;
    }
}

// ======================================================================
// Kernel 4: final combine
// ======================================================================
__global__ void k_out(float* __restrict__ out) {
    int b = blockIdx.x * 256 + threadIdx.x;
    if (b < BB) {
        float s = g_scabs[b];
        #pragma unroll
        for (int i = 0; i < NSLICE; i++) s += g_prel[i * BB + b];
        out[b] = GAMMA_F - s;
    }
}

// ======================================================================
// launcher
// ======================================================================
extern "C" void kernel_launch(void* const* d_in, const int* in_sizes, int n_in,
                              void* d_out, int out_size)
{
    const int*   x     = (const int*)  d_in[0];
    const float* e_emb = (const float*)d_in[1];
    const float* r_emb = (const float*)d_in[2];
    const float* d_frq = (const float*)d_in[3];
    const float* d_phi = (const float*)d_in[4];
    const float* d_amp = (const float*)d_in[5];
    const float* m_frq = (const float*)d_in[6];
    const float* m_phi = (const float*)d_in[7];
    const float* m_amp = (const float*)d_in[8];
    const float* w_e   = (const float*)d_in[9];
    const float* w_rp  = (const float*)d_in[10];
    float* out = (float*)d_out;

    // x arrives as int64 reported in int32 words; infer element stride.
    int xs = in_sizes[0] / (BB * NCOL);
    if (xs < 1) xs = 1;

    cudaFuncSetAttribute(k_rel, cudaFuncAttributeMaxDynamicSharedMemorySize, 128 * 1024);

    k_wc<<<512, 256>>>(w_e);
    k_tbuild<<<1000, 128>>>();
    k_gather<<<BB, 256>>>(x, xs, e_emb, r_emb, d_frq, d_phi, d_amp,
                          m_frq, m_phi, m_amp, w_rp);
    k_gemm<<<dim3(2, 128), 256>>>(e_emb, x, xs);
    k_rel<<<NSLICE * RB, 512, 128000>>>();
    k_out<<<32, 256>>>(out);
}